// round 2
// baseline (speedup 1.0000x reference)
#include <cuda_runtime.h>
#include <cstdint>

#define BB 8
#define CC_ 256
#define NN 4096
#define DD 32

// Scratch (device globals — no allocations allowed)
__device__ float g_q[(size_t)BB * NN * DD];          // [B][N][32]
__device__ float g_k[(size_t)BB * NN * DD];          // [B][N][32]
__device__ float g_v[(size_t)BB * NN * CC_];         // [B][N][256]  (transposed vs input layout)

// ---------------------------------------------------------------------------
// Kernel A: q/k projections.  q[b,n,d] = sum_c Wq[d,c] * x[b,c,n] + bq[d]
// grid (32, 8), 128 threads; each thread owns one pixel n, accumulates 32 q + 32 k.
// ---------------------------------------------------------------------------
__global__ __launch_bounds__(128)
void qk_proj_kernel(const float* __restrict__ x,
                    const float* __restrict__ Wq, const float* __restrict__ bq,
                    const float* __restrict__ Wk, const float* __restrict__ bk)
{
    __shared__ float xs[32][128];
    __shared__ float wqs[32][32];
    __shared__ float wks[32][32];

    const int b = blockIdx.y;
    const int n = blockIdx.x * 128 + threadIdx.x;
    const int t = threadIdx.x;

    float accq[32], acck[32];
#pragma unroll
    for (int d = 0; d < 32; d++) { accq[d] = 0.f; acck[d] = 0.f; }

    for (int c0 = 0; c0 < CC_; c0 += 32) {
        for (int i = 0; i < 32; i++)
            xs[i][t] = x[((size_t)b * CC_ + c0 + i) * NN + n];
        for (int idx = t; idx < 1024; idx += 128) {
            int d = idx >> 5, ci = idx & 31;
            wqs[d][ci] = Wq[d * CC_ + c0 + ci];
            wks[d][ci] = Wk[d * CC_ + c0 + ci];
        }
        __syncthreads();
#pragma unroll 4
        for (int ci = 0; ci < 32; ci++) {
            float xv = xs[ci][t];
#pragma unroll
            for (int d = 0; d < 32; d++) {
                accq[d] += wqs[d][ci] * xv;
                acck[d] += wks[d][ci] * xv;
            }
        }
        __syncthreads();
    }

    float* qo = &g_q[((size_t)b * NN + n) * DD];
    float* ko = &g_k[((size_t)b * NN + n) * DD];
#pragma unroll
    for (int d = 0; d < 32; d += 4) {
        float4 q4 = make_float4(accq[d] + bq[d], accq[d+1] + bq[d+1],
                                accq[d+2] + bq[d+2], accq[d+3] + bq[d+3]);
        float4 k4 = make_float4(acck[d] + bk[d], acck[d+1] + bk[d+1],
                                acck[d+2] + bk[d+2], acck[d+3] + bk[d+3]);
        *(float4*)&qo[d] = q4;
        *(float4*)&ko[d] = k4;
    }
}

// ---------------------------------------------------------------------------
// Kernel B: v projection.  v[b,n,c] = sum_k Wv[c,k] * x[b,k,n] + bv[c]
// grid (32, 4, 8), 256 threads; block tile = 128n x 64c; thread microtile 4n x 8c.
// ---------------------------------------------------------------------------
__global__ __launch_bounds__(256)
void v_proj_kernel(const float* __restrict__ x,
                   const float* __restrict__ Wv, const float* __restrict__ bv)
{
    __shared__ float xs[16][128];
    __shared__ float ws[64][17];

    const int b  = blockIdx.z;
    const int n0 = blockIdx.x * 128;
    const int c0 = blockIdx.y * 64;
    const int t  = threadIdx.x;
    const int tn = t & 31;   // n group (4 each)
    const int tc = t >> 5;   // c group (8 each)

    float acc[4][8];
#pragma unroll
    for (int r = 0; r < 4; r++)
#pragma unroll
        for (int s = 0; s < 8; s++) acc[r][s] = 0.f;

    for (int k0 = 0; k0 < CC_; k0 += 16) {
        for (int idx = t; idx < 2048; idx += 256) {
            int kk = idx >> 7, nn = idx & 127;
            xs[kk][nn] = x[((size_t)b * CC_ + k0 + kk) * NN + n0 + nn];
        }
        for (int idx = t; idx < 1024; idx += 256) {
            int c = idx >> 4, kk = idx & 15;
            ws[c][kk] = Wv[(c0 + c) * CC_ + k0 + kk];
        }
        __syncthreads();
#pragma unroll
        for (int kk = 0; kk < 16; kk++) {
            float4 a4 = *(const float4*)&xs[kk][tn * 4];
            float av[4] = {a4.x, a4.y, a4.z, a4.w};
#pragma unroll
            for (int s = 0; s < 8; s++) {
                float wv = ws[tc * 8 + s][kk];
#pragma unroll
                for (int r = 0; r < 4; r++) acc[r][s] += av[r] * wv;
            }
        }
        __syncthreads();
    }

#pragma unroll
    for (int r = 0; r < 4; r++) {
        float* vo = &g_v[((size_t)b * NN + n0 + tn * 4 + r) * CC_ + c0 + tc * 8];
        float4 o1 = make_float4(acc[r][0] + bv[c0 + tc*8 + 0], acc[r][1] + bv[c0 + tc*8 + 1],
                                acc[r][2] + bv[c0 + tc*8 + 2], acc[r][3] + bv[c0 + tc*8 + 3]);
        float4 o2 = make_float4(acc[r][4] + bv[c0 + tc*8 + 4], acc[r][5] + bv[c0 + tc*8 + 5],
                                acc[r][6] + bv[c0 + tc*8 + 6], acc[r][7] + bv[c0 + tc*8 + 7]);
        *(float4*)&vo[0] = o1;
        *(float4*)&vo[4] = o2;
    }
}

// ---------------------------------------------------------------------------
// Kernel C: fused flash attention.
// grid (64, 8), 256 threads. Block = 64 queries x 256 channels.
// Online softmax over all 4096 keys in tiles of 64; PV as shared-mem GEMM
// with 8q x 8c register microtiles.
// ---------------------------------------------------------------------------
// dynamic smem layout (floats):
//   qs  [64][33]   = 2112
//   ks  [64][33]   = 2112
//   p   [64][65]   = 4160
//   vs  [16][256]  = 4096
//   m/l/corr 3*64  = 192
#define SM_QS   0
#define SM_KS   (SM_QS + 64*33)
#define SM_P    (SM_KS + 64*33)
#define SM_VS   (SM_P  + 64*65)
#define SM_M    (SM_VS + 16*256)
#define SM_L    (SM_M + 64)
#define SM_CORR (SM_L + 64)
#define SM_FLOATS (SM_CORR + 64)
#define ATTN_SMEM_BYTES (SM_FLOATS * 4)

extern __shared__ float smem[];

__global__ __launch_bounds__(256, 2)
void attn_kernel(float* __restrict__ out)
{
    float* qs   = smem + SM_QS;
    float* ks   = smem + SM_KS;
    float* p    = smem + SM_P;
    float* vs   = smem + SM_VS;
    float* mrow = smem + SM_M;
    float* lrow = smem + SM_L;
    float* crow = smem + SM_CORR;

    const int b  = blockIdx.y;
    const int q0 = blockIdx.x * 64;
    const int t  = threadIdx.x;

    // S-compute mapping: 16x16 threads, each 4q x 4j
    const int sq = (t >> 4) * 4;
    const int sj = (t & 15) * 4;
    // PV mapping: 8x32 threads, each 8q x 8c
    const int pq0 = (t >> 5) * 8;
    const int pc0 = (t & 31) * 8;

    // load q tile
    for (int idx = t; idx < 64 * 32; idx += 256) {
        int r = idx >> 5, kk = idx & 31;
        qs[r * 33 + kk] = g_q[((size_t)b * NN + q0 + r) * DD + kk];
    }
    if (t < 64) { mrow[t] = -1e30f; lrow[t] = 0.f; }

    float acc[8][8];
#pragma unroll
    for (int r = 0; r < 8; r++)
#pragma unroll
        for (int s = 0; s < 8; s++) acc[r][s] = 0.f;

    __syncthreads();

    for (int j0 = 0; j0 < NN; j0 += 64) {
        // load k tile
        for (int idx = t; idx < 64 * 32; idx += 256) {
            int r = idx >> 5, kk = idx & 31;
            ks[r * 33 + kk] = g_k[((size_t)b * NN + j0 + r) * DD + kk];
        }
        __syncthreads();

        // S = q . k  (no 1/sqrt(d) scale — matches reference)
        float s4[4][4];
#pragma unroll
        for (int r = 0; r < 4; r++)
#pragma unroll
            for (int s = 0; s < 4; s++) s4[r][s] = 0.f;
#pragma unroll
        for (int kk = 0; kk < 32; kk++) {
            float qr[4], kr[4];
#pragma unroll
            for (int r = 0; r < 4; r++) qr[r] = qs[(sq + r) * 33 + kk];
#pragma unroll
            for (int s = 0; s < 4; s++) kr[s] = ks[(sj + s) * 33 + kk];
#pragma unroll
            for (int r = 0; r < 4; r++)
#pragma unroll
                for (int s = 0; s < 4; s++) s4[r][s] += qr[r] * kr[s];
        }
#pragma unroll
        for (int r = 0; r < 4; r++)
#pragma unroll
            for (int s = 0; s < 4; s++)
                p[(sq + r) * 65 + sj + s] = s4[r][s];
        __syncthreads();

        // online softmax, one row per thread (threads 0..63)
        if (t < 64) {
            const int q = t;
            float mold = mrow[q];
            float mx = mold;
            for (int j = 0; j < 64; j++) mx = fmaxf(mx, p[q * 65 + j]);
            float corr = __expf(mold - mx);
            float sum = 0.f;
            for (int j = 0; j < 64; j++) {
                float e = __expf(p[q * 65 + j] - mx);
                p[q * 65 + j] = e;
                sum += e;
            }
            lrow[q] = lrow[q] * corr + sum;
            mrow[q] = mx;
            crow[q] = corr;
        }
        __syncthreads();

        // rescale accumulators
        float cf[8];
#pragma unroll
        for (int r = 0; r < 8; r++) cf[r] = crow[pq0 + r];
#pragma unroll
        for (int r = 0; r < 8; r++)
#pragma unroll
            for (int s = 0; s < 8; s++) acc[r][s] *= cf[r];

        // PV: O[64q][256c] += P[64q][64j] * V[64j][256c], j chunks of 16
        for (int jc = 0; jc < 64; jc += 16) {
            for (int idx = t; idx < 16 * 256; idx += 256) {
                int jj = idx >> 8, c = idx & 255;
                vs[jj * 256 + c] = g_v[((size_t)b * NN + j0 + jc + jj) * CC_ + c];
            }
            __syncthreads();
#pragma unroll 4
            for (int jj = 0; jj < 16; jj++) {
                float pq[8];
#pragma unroll
                for (int r = 0; r < 8; r++) pq[r] = p[(pq0 + r) * 65 + jc + jj];
                float4 v1 = *(const float4*)&vs[jj * 256 + pc0];
                float4 v2 = *(const float4*)&vs[jj * 256 + pc0 + 4];
                float vv[8] = {v1.x, v1.y, v1.z, v1.w, v2.x, v2.y, v2.z, v2.w};
#pragma unroll
                for (int r = 0; r < 8; r++)
#pragma unroll
                    for (int s = 0; s < 8; s++) acc[r][s] += pq[r] * vv[s];
            }
            __syncthreads();
        }
    }

    // epilogue: out[b][c][n], thread's 8 queries are contiguous n
    float invl[8];
#pragma unroll
    for (int r = 0; r < 8; r++) invl[r] = 1.0f / lrow[pq0 + r];
#pragma unroll
    for (int s = 0; s < 8; s++) {
        const int c = pc0 + s;
        float* op = &out[((size_t)b * CC_ + c) * NN + q0 + pq0];
        float4 o1 = make_float4(acc[0][s] * invl[0], acc[1][s] * invl[1],
                                acc[2][s] * invl[2], acc[3][s] * invl[3]);
        float4 o2 = make_float4(acc[4][s] * invl[4], acc[5][s] * invl[5],
                                acc[6][s] * invl[6], acc[7][s] * invl[7]);
        *(float4*)&op[0] = o1;
        *(float4*)&op[4] = o2;
    }
}

// ---------------------------------------------------------------------------
extern "C" void kernel_launch(void* const* d_in, const int* in_sizes, int n_in,
                              void* d_out, int out_size)
{
    const float* x  = (const float*)d_in[0];
    const float* Wq = (const float*)d_in[1];
    const float* bq = (const float*)d_in[2];
    const float* Wk = (const float*)d_in[3];
    const float* bk = (const float*)d_in[4];
    const float* Wv = (const float*)d_in[5];
    const float* bv = (const float*)d_in[6];
    float* out = (float*)d_out;

    qk_proj_kernel<<<dim3(32, 8), 128>>>(x, Wq, bq, Wk, bk);
    v_proj_kernel<<<dim3(32, 4, 8), 256>>>(x, Wv, bv);

    cudaFuncSetAttribute(attn_kernel, cudaFuncAttributeMaxDynamicSharedMemorySize,
                         ATTN_SMEM_BYTES);
    attn_kernel<<<dim3(64, 8), 256, ATTN_SMEM_BYTES>>>(out);
}

// round 3
// speedup vs baseline: 2.7646x; 2.7646x over previous
#include <cuda_runtime.h>
#include <cstdint>

#define BB 8
#define CC_ 256
#define NN 4096
#define DD 32

// Scratch (device globals — no allocations allowed)
__device__ float  g_q[(size_t)BB * NN * DD];            // [b][n][32] row-major
__device__ float  g_k[(size_t)BB * NN * DD];            // [b][n][32] row-major
// V pre-permuted into mma B-fragment layout:
// float2 slot [(b*64+jt)*8 + ks][ct][lane] = { V[jt*64+ks*8+(lane&3)][ct*8+lane/4],
//                                              V[jt*64+ks*8+(lane&3)+4][ct*8+lane/4] }
__device__ float2 g_vf[(size_t)BB * 64 * 8 * 32 * 32];

// ---------------------------------------------------------------------------
__device__ __forceinline__ float to_tf32(float x) {
    unsigned u;
    asm("cvt.rna.tf32.f32 %0, %1;" : "=r"(u) : "f"(x));
    return __uint_as_float(u);
}

__device__ __forceinline__ void mma_tf32(float4& d, float4 a, float2 b) {
    asm volatile(
        "mma.sync.aligned.m16n8k8.row.col.f32.tf32.tf32.f32 "
        "{%0,%1,%2,%3}, {%4,%5,%6,%7}, {%8,%9}, {%0,%1,%2,%3};\n"
        : "+f"(d.x), "+f"(d.y), "+f"(d.z), "+f"(d.w)
        : "r"(__float_as_uint(a.x)), "r"(__float_as_uint(a.y)),
          "r"(__float_as_uint(a.z)), "r"(__float_as_uint(a.w)),
          "r"(__float_as_uint(b.x)), "r"(__float_as_uint(b.y)));
}

// ---------------------------------------------------------------------------
// Kernel A: q/k projections (unchanged, 57us).  Outputs row-major [b][n][32].
// ---------------------------------------------------------------------------
__global__ __launch_bounds__(128)
void qk_proj_kernel(const float* __restrict__ x,
                    const float* __restrict__ Wq, const float* __restrict__ bq,
                    const float* __restrict__ Wk, const float* __restrict__ bk)
{
    __shared__ float xs[32][128];
    __shared__ float wqs[32][32];
    __shared__ float wks[32][32];

    const int b = blockIdx.y;
    const int n = blockIdx.x * 128 + threadIdx.x;
    const int t = threadIdx.x;

    float accq[32], acck[32];
#pragma unroll
    for (int d = 0; d < 32; d++) { accq[d] = 0.f; acck[d] = 0.f; }

    for (int c0 = 0; c0 < CC_; c0 += 32) {
        for (int i = 0; i < 32; i++)
            xs[i][t] = x[((size_t)b * CC_ + c0 + i) * NN + n];
        for (int idx = t; idx < 1024; idx += 128) {
            int d = idx >> 5, ci = idx & 31;
            wqs[d][ci] = Wq[d * CC_ + c0 + ci];
            wks[d][ci] = Wk[d * CC_ + c0 + ci];
        }
        __syncthreads();
#pragma unroll 4
        for (int ci = 0; ci < 32; ci++) {
            float xv = xs[ci][t];
#pragma unroll
            for (int d = 0; d < 32; d++) {
                accq[d] += wqs[d][ci] * xv;
                acck[d] += wks[d][ci] * xv;
            }
        }
        __syncthreads();
    }

    float* qo = &g_q[((size_t)b * NN + n) * DD];
    float* ko = &g_k[((size_t)b * NN + n) * DD];
#pragma unroll
    for (int d = 0; d < 32; d += 4) {
        float4 q4 = make_float4(accq[d] + bq[d], accq[d+1] + bq[d+1],
                                accq[d+2] + bq[d+2], accq[d+3] + bq[d+3]);
        float4 k4 = make_float4(acck[d] + bk[d], acck[d+1] + bk[d+1],
                                acck[d+2] + bk[d+2], acck[d+3] + bk[d+3]);
        *(float4*)&qo[d] = q4;
        *(float4*)&ko[d] = k4;
    }
}

// ---------------------------------------------------------------------------
// Kernel B: v projection. block = 64n x 64c, 128 threads, microtile 4n x 8c.
// fp32 FFMA compute; epilogue converts to tf32 and writes B-fragment layout.
// grid (64, 4, 8)
// ---------------------------------------------------------------------------
__global__ __launch_bounds__(128)
void v_proj_kernel(const float* __restrict__ x,
                   const float* __restrict__ Wv, const float* __restrict__ bv)
{
    __shared__ float buf[64 * 65];   // phase1: xs[16*64] + ws[64*17]; phase2: vsm[64][65]
    float* xs = buf;                 // [16][64]
    float* ws = buf + 1024;          // [64][17]

    const int jt = blockIdx.x;
    const int cb = blockIdx.y;
    const int b  = blockIdx.z;
    const int n0 = jt * 64;
    const int c0 = cb * 64;
    const int t  = threadIdx.x;
    const int tn = t & 15;    // 16 n-groups of 4
    const int tc = t >> 4;    // 8 c-groups of 8

    float acc[4][8];
#pragma unroll
    for (int r = 0; r < 4; r++)
#pragma unroll
        for (int s = 0; s < 8; s++) acc[r][s] = 0.f;

    for (int k0 = 0; k0 < CC_; k0 += 16) {
        for (int i = 0; i < 8; i++) {
            int idx = t + 128 * i;                 // 0..1023
            int kk = idx >> 6, nn = idx & 63;
            xs[kk * 64 + nn] = x[((size_t)b * CC_ + k0 + kk) * NN + n0 + nn];
        }
        for (int i = 0; i < 8; i++) {
            int idx = t + 128 * i;
            int c = idx >> 4, kk = idx & 15;
            ws[c * 17 + kk] = Wv[(c0 + c) * CC_ + k0 + kk];
        }
        __syncthreads();
#pragma unroll
        for (int kk = 0; kk < 16; kk++) {
            float4 a = *(const float4*)&xs[kk * 64 + tn * 4];
#pragma unroll
            for (int s = 0; s < 8; s++) {
                float w = ws[(tc * 8 + s) * 17 + kk];
                acc[0][s] += a.x * w;
                acc[1][s] += a.y * w;
                acc[2][s] += a.z * w;
                acc[3][s] += a.w * w;
            }
        }
        __syncthreads();
    }

    // phase 2: stage tile (tf32-rounded) into vsm, then permuted global store
    float* vsm = buf;  // [64][65]
#pragma unroll
    for (int r = 0; r < 4; r++)
#pragma unroll
        for (int s = 0; s < 8; s++) {
            float val = acc[r][s] + bv[c0 + tc * 8 + s];
            vsm[(tn * 4 + r) * 65 + tc * 8 + s] = to_tf32(val);
        }
    __syncthreads();

#pragma unroll
    for (int i = 0; i < 16; i++) {
        int idx = t + 128 * i;                     // 0..2047
        int ln  = idx & 31;
        int ctl = (idx >> 5) & 7;
        int ks  = idx >> 8;                        // 0..7
        int r0  = ks * 8 + (ln & 3);
        int c   = ctl * 8 + (ln >> 2);
        float2 v2 = make_float2(vsm[r0 * 65 + c], vsm[(r0 + 4) * 65 + c]);
        g_vf[(((size_t)(b * 64 + jt) * 8 + ks) * 32 + (cb * 8 + ctl)) * 32 + ln] = v2;
    }
}

// ---------------------------------------------------------------------------
// Kernel C: fused flash attention on tensor cores (tf32 mma.sync).
// grid (64, 8), 256 threads (8 warps). CTA = 64 queries x 256 channels.
// S = QK^T with 2-term tf32 split (near-fp32); PV single-pass tf32.
// ---------------------------------------------------------------------------
// smem layout (floats):
#define SM_QF    0                       // float4 [pass(2)][mt(4)][ks(4)] stride 34, lanes 32 -> 1088 f4 = 4352
#define SM_KF    4352                    // float2 [pass*4+ks (8)] stride 260: nt(8)*32+lane -> 2080 f2 = 4160
#define SM_P     (SM_KF + 4160)          // p[64][68] = 4352
#define SM_VS    (SM_P + 4352)           // float2 [ks(4)][ct(32)][lane(32)] = 4096 f2 = 8192
#define SM_M     (SM_VS + 8192)
#define SM_L     (SM_M + 64)
#define SM_CORR  (SM_L + 64)
#define SM_TOT   (SM_CORR + 64)          // 21248 floats
#define ATTN_SMEM_BYTES (SM_TOT * 4)

extern __shared__ float smem[];

__global__ __launch_bounds__(256, 2)
void attn_kernel(float* __restrict__ out)
{
    float*  qff  = smem + SM_QF;
    float4* qf4  = (float4*)(smem + SM_QF);
    float*  kff  = smem + SM_KF;
    float2* kf2  = (float2*)(smem + SM_KF);
    float*  p    = smem + SM_P;
    float2* vs2  = (float2*)(smem + SM_VS);
    float4* vs4  = (float4*)(smem + SM_VS);
    float*  mrow = smem + SM_M;
    float*  lrow = smem + SM_L;
    float*  crow = smem + SM_CORR;

    const int b  = blockIdx.y;
    const int q0 = blockIdx.x * 64;
    const int t  = threadIdx.x;
    const int wid  = t >> 5;
    const int lane = t & 31;
    const int g    = lane >> 2;       // fragment row group
    const int i4   = lane & 3;        // fragment col group

    // S-phase warp map: 16q x 32j tiles
    const int sm = wid & 3;           // m-tile 0..3 (16 rows each)
    const int sn = wid >> 2;          // 0..1 (32 cols each)
    // PV warp map: 32q x 64c tiles
    const int pm = wid & 1;           // 0..1 (32 rows)
    const int pn = wid >> 1;          // 0..3 (64 cols)

    // ---- stage Q fragments (hi/lo) once ----
    for (int idx = t; idx < 2048; idx += 256) {
        int r = idx >> 5, d = idx & 31;
        float val = g_q[((size_t)b * NN + q0 + r) * DD + d];
        float hi = to_tf32(val);
        float lo = to_tf32(val - hi);
        int mt = r >> 4, ks = d >> 3;
        int ln = (r & 7) * 4 + (d & 3);
        int comp = ((r >> 3) & 1) + 2 * ((d >> 2) & 1);
        qff[((( (0*4 + mt) * 4 + ks) * 34) + ln) * 4 + comp] = hi;
        qff[((( (1*4 + mt) * 4 + ks) * 34) + ln) * 4 + comp] = lo;
    }
    if (t < 64) { mrow[t] = -1e30f; lrow[t] = 0.f; }

    float4 o[2][8];
#pragma unroll
    for (int mt = 0; mt < 2; mt++)
#pragma unroll
        for (int nt = 0; nt < 8; nt++) o[mt][nt] = make_float4(0.f, 0.f, 0.f, 0.f);

    __syncthreads();

    for (int jt = 0; jt < 64; jt++) {
        // ---- stage K fragments (hi/lo) ----
        for (int idx = t; idx < 2048; idx += 256) {
            int j = idx >> 5, d = idx & 31;
            float val = g_k[((size_t)b * NN + jt * 64 + j) * DD + d];
            float hi = to_tf32(val);
            float lo = to_tf32(val - hi);
            int ks = d >> 3, nt = j >> 3;
            int ln = (j & 7) * 4 + (d & 3);
            int comp = (d >> 2) & 1;
            kff[((0*4 + ks) * 260 + nt * 32 + ln) * 2 + comp] = hi;
            kff[((1*4 + ks) * 260 + nt * 32 + ln) * 2 + comp] = lo;
        }
        __syncthreads();

        // ---- S = Q.K^T  (hi*hi + hi*lo + lo*hi) ----
        float4 sacc[4];
#pragma unroll
        for (int nt = 0; nt < 4; nt++) sacc[nt] = make_float4(0.f, 0.f, 0.f, 0.f);
#pragma unroll
        for (int ks = 0; ks < 4; ks++) {
            float4 ah = qf4[((0*4 + sm) * 4 + ks) * 34 + lane];
            float4 al = qf4[((1*4 + sm) * 4 + ks) * 34 + lane];
#pragma unroll
            for (int nt = 0; nt < 4; nt++) {
                float2 bh = kf2[(0*4 + ks) * 260 + (sn * 4 + nt) * 32 + lane];
                float2 bl = kf2[(1*4 + ks) * 260 + (sn * 4 + nt) * 32 + lane];
                mma_tf32(sacc[nt], ah, bh);
                mma_tf32(sacc[nt], ah, bl);
                mma_tf32(sacc[nt], al, bh);
            }
        }
#pragma unroll
        for (int nt = 0; nt < 4; nt++) {
            int row = sm * 16 + g;
            int col = sn * 32 + nt * 8 + i4 * 2;
            *(float2*)&p[row * 68 + col]       = make_float2(sacc[nt].x, sacc[nt].y);
            *(float2*)&p[(row + 8) * 68 + col] = make_float2(sacc[nt].z, sacc[nt].w);
        }
        __syncthreads();

        // ---- online softmax: 4 threads per row, 16 cols each ----
        {
            int r = t >> 2, qd = t & 3;
            float* pr = p + r * 68 + qd * 16;
            float4 x0 = *(float4*)(pr + 0);
            float4 x1 = *(float4*)(pr + 4);
            float4 x2 = *(float4*)(pr + 8);
            float4 x3 = *(float4*)(pr + 12);
            float lm = fmaxf(fmaxf(fmaxf(x0.x, x0.y), fmaxf(x0.z, x0.w)),
                             fmaxf(fmaxf(x1.x, x1.y), fmaxf(x1.z, x1.w)));
            lm = fmaxf(lm, fmaxf(fmaxf(fmaxf(x2.x, x2.y), fmaxf(x2.z, x2.w)),
                                 fmaxf(fmaxf(x3.x, x3.y), fmaxf(x3.z, x3.w))));
            lm = fmaxf(lm, __shfl_xor_sync(0xffffffffu, lm, 1, 4));
            lm = fmaxf(lm, __shfl_xor_sync(0xffffffffu, lm, 2, 4));
            float mold = mrow[r];
            float mx = fmaxf(mold, lm);
            float4 e0, e1, e2, e3;
            e0.x = __expf(x0.x - mx); e0.y = __expf(x0.y - mx);
            e0.z = __expf(x0.z - mx); e0.w = __expf(x0.w - mx);
            e1.x = __expf(x1.x - mx); e1.y = __expf(x1.y - mx);
            e1.z = __expf(x1.z - mx); e1.w = __expf(x1.w - mx);
            e2.x = __expf(x2.x - mx); e2.y = __expf(x2.y - mx);
            e2.z = __expf(x2.z - mx); e2.w = __expf(x2.w - mx);
            e3.x = __expf(x3.x - mx); e3.y = __expf(x3.y - mx);
            e3.z = __expf(x3.z - mx); e3.w = __expf(x3.w - mx);
            float s = (e0.x + e0.y + e0.z + e0.w) + (e1.x + e1.y + e1.z + e1.w)
                    + (e2.x + e2.y + e2.z + e2.w) + (e3.x + e3.y + e3.z + e3.w);
            // store tf32-rounded P for the mma
            e0.x = to_tf32(e0.x); e0.y = to_tf32(e0.y); e0.z = to_tf32(e0.z); e0.w = to_tf32(e0.w);
            e1.x = to_tf32(e1.x); e1.y = to_tf32(e1.y); e1.z = to_tf32(e1.z); e1.w = to_tf32(e1.w);
            e2.x = to_tf32(e2.x); e2.y = to_tf32(e2.y); e2.z = to_tf32(e2.z); e2.w = to_tf32(e2.w);
            e3.x = to_tf32(e3.x); e3.y = to_tf32(e3.y); e3.z = to_tf32(e3.z); e3.w = to_tf32(e3.w);
            *(float4*)(pr + 0)  = e0;
            *(float4*)(pr + 4)  = e1;
            *(float4*)(pr + 8)  = e2;
            *(float4*)(pr + 12) = e3;
            s += __shfl_xor_sync(0xffffffffu, s, 1, 4);
            s += __shfl_xor_sync(0xffffffffu, s, 2, 4);
            if (qd == 0) {
                float corr = __expf(mold - mx);
                crow[r] = corr;
                mrow[r] = mx;
                lrow[r] = lrow[r] * corr + s;
            }
        }
        __syncthreads();

        // ---- rescale accumulators ----
#pragma unroll
        for (int mt = 0; mt < 2; mt++) {
            float cf0 = crow[pm * 32 + mt * 16 + g];
            float cf1 = crow[pm * 32 + mt * 16 + g + 8];
#pragma unroll
            for (int nt = 0; nt < 8; nt++) {
                o[mt][nt].x *= cf0; o[mt][nt].y *= cf0;
                o[mt][nt].z *= cf1; o[mt][nt].w *= cf1;
            }
        }

        // ---- PV: two 32KB V chunks (ks 0..3 then 4..7) ----
#pragma unroll
        for (int ch = 0; ch < 2; ch++) {
            const float4* src = (const float4*)(g_vf + ((size_t)(b * 64 + jt) * 8 + ch * 4) * 1024);
            for (int idx = t; idx < 2048; idx += 256)
                vs4[idx] = src[idx];
            __syncthreads();
#pragma unroll
            for (int ks = 0; ks < 4; ks++) {
                int jc = (ch * 4 + ks) * 8 + i4;
                float4 a0, a1;
                a0.x = p[(pm * 32 + g) * 68 + jc];
                a0.y = p[(pm * 32 + g + 8) * 68 + jc];
                a0.z = p[(pm * 32 + g) * 68 + jc + 4];
                a0.w = p[(pm * 32 + g + 8) * 68 + jc + 4];
                a1.x = p[(pm * 32 + 16 + g) * 68 + jc];
                a1.y = p[(pm * 32 + 16 + g + 8) * 68 + jc];
                a1.z = p[(pm * 32 + 16 + g) * 68 + jc + 4];
                a1.w = p[(pm * 32 + 16 + g + 8) * 68 + jc + 4];
#pragma unroll
                for (int nt = 0; nt < 8; nt++) {
                    float2 bv = vs2[(ks * 32 + pn * 8 + nt) * 32 + lane];
                    mma_tf32(o[0][nt], a0, bv);
                    mma_tf32(o[1][nt], a1, bv);
                }
            }
            __syncthreads();
        }
    }

    // ---- epilogue: out[b][c][n], normalize by l ----
#pragma unroll
    for (int mt = 0; mt < 2; mt++) {
        int qb = q0 + pm * 32 + mt * 16;
        float il0 = 1.0f / lrow[pm * 32 + mt * 16 + g];
        float il1 = 1.0f / lrow[pm * 32 + mt * 16 + g + 8];
#pragma unroll
        for (int nt = 0; nt < 8; nt++) {
            int c = pn * 64 + nt * 8 + i4 * 2;
            out[((size_t)b * CC_ + c)     * NN + qb + g]     = o[mt][nt].x * il0;
            out[((size_t)b * CC_ + c + 1) * NN + qb + g]     = o[mt][nt].y * il0;
            out[((size_t)b * CC_ + c)     * NN + qb + g + 8] = o[mt][nt].z * il1;
            out[((size_t)b * CC_ + c + 1) * NN + qb + g + 8] = o[mt][nt].w * il1;
        }
    }
}

// ---------------------------------------------------------------------------
extern "C" void kernel_launch(void* const* d_in, const int* in_sizes, int n_in,
                              void* d_out, int out_size)
{
    const float* x  = (const float*)d_in[0];
    const float* Wq = (const float*)d_in[1];
    const float* bq = (const float*)d_in[2];
    const float* Wk = (const float*)d_in[3];
    const float* bk = (const float*)d_in[4];
    const float* Wv = (const float*)d_in[5];
    const float* bv = (const float*)d_in[6];
    float* out = (float*)d_out;

    qk_proj_kernel<<<dim3(32, 8), 128>>>(x, Wq, bq, Wk, bk);
    v_proj_kernel<<<dim3(64, 4, 8), 128>>>(x, Wv, bv);

    cudaFuncSetAttribute(attn_kernel, cudaFuncAttributeMaxDynamicSharedMemorySize,
                         ATTN_SMEM_BYTES);
    attn_kernel<<<dim3(64, 8), 256, ATTN_SMEM_BYTES>>>(out);
}

// round 6
// speedup vs baseline: 4.0148x; 1.4522x over previous
#include <cuda_runtime.h>
#include <cuda_fp16.h>
#include <cstdint>

#define BB 8
#define CC_ 256
#define NN 4096
#define DD 32

// Scratch (device globals — no allocations allowed)
__device__ float    g_q[(size_t)BB * NN * DD];    // [b][n][32]
__device__ float    g_k[(size_t)BB * NN * DD];    // [b][n][32]
// V pre-packed in m16n8k16 B-fragment half2 layout, one 8192-uint block per (b, jtile):
//   block[((kc*32 + ct)*2 + comp)*32 + lane]   kc:4, ct:32, comp:2, lane:32 -> 8192
__device__ uint32_t g_vf[(size_t)BB * 64 * 8192];

// ---------------------------------------------------------------------------
__device__ __forceinline__ void mma_f16(float4& d, uint32_t a0, uint32_t a1,
                                        uint32_t a2, uint32_t a3,
                                        uint32_t b0, uint32_t b1) {
    asm volatile(
        "mma.sync.aligned.m16n8k16.row.col.f32.f16.f16.f32 "
        "{%0,%1,%2,%3}, {%4,%5,%6,%7}, {%8,%9}, {%0,%1,%2,%3};\n"
        : "+f"(d.x), "+f"(d.y), "+f"(d.z), "+f"(d.w)
        : "r"(a0), "r"(a1), "r"(a2), "r"(a3), "r"(b0), "r"(b1));
}

__device__ __forceinline__ uint32_t pack_h2(float a, float b) {
    __half2 h = __halves2half2(__float2half_rn(a), __float2half_rn(b));
    return *(uint32_t*)&h;
}

// ---------------------------------------------------------------------------
// Kernel A: q/k projections. Outputs row-major [b][n][32] fp32.
// ---------------------------------------------------------------------------
__global__ __launch_bounds__(128)
void qk_proj_kernel(const float* __restrict__ x,
                    const float* __restrict__ Wq, const float* __restrict__ bq,
                    const float* __restrict__ Wk, const float* __restrict__ bk)
{
    __shared__ float xs[32][128];
    __shared__ float wqs[32][32];
    __shared__ float wks[32][32];

    const int b = blockIdx.y;
    const int n = blockIdx.x * 128 + threadIdx.x;
    const int t = threadIdx.x;

    float accq[32], acck[32];
#pragma unroll
    for (int d = 0; d < 32; d++) { accq[d] = 0.f; acck[d] = 0.f; }

    for (int c0 = 0; c0 < CC_; c0 += 32) {
        for (int i = 0; i < 32; i++)
            xs[i][t] = x[((size_t)b * CC_ + c0 + i) * NN + n];
        for (int idx = t; idx < 1024; idx += 128) {
            int d = idx >> 5, ci = idx & 31;
            wqs[d][ci] = Wq[d * CC_ + c0 + ci];
            wks[d][ci] = Wk[d * CC_ + c0 + ci];
        }
        __syncthreads();
#pragma unroll 4
        for (int ci = 0; ci < 32; ci++) {
            float xv = xs[ci][t];
#pragma unroll
            for (int d = 0; d < 32; d++) {
                accq[d] += wqs[d][ci] * xv;
                acck[d] += wks[d][ci] * xv;
            }
        }
        __syncthreads();
    }

    float* qo = &g_q[((size_t)b * NN + n) * DD];
    float* ko = &g_k[((size_t)b * NN + n) * DD];
#pragma unroll
    for (int d = 0; d < 32; d += 4) {
        float4 q4 = make_float4(accq[d] + bq[d], accq[d+1] + bq[d+1],
                                accq[d+2] + bq[d+2], accq[d+3] + bq[d+3]);
        float4 k4 = make_float4(acck[d] + bk[d], acck[d+1] + bk[d+1],
                                acck[d+2] + bk[d+2], acck[d+3] + bk[d+3]);
        *(float4*)&qo[d] = q4;
        *(float4*)&ko[d] = k4;
    }
}

// ---------------------------------------------------------------------------
// Kernel B: v projection (fp32 FFMA). Epilogue packs fp16 B-fragments.
// grid (64, 4, 8), 128 threads; block tile 64n x 64c, microtile 4n x 8c.
// ---------------------------------------------------------------------------
__global__ __launch_bounds__(128)
void v_proj_kernel(const float* __restrict__ x,
                   const float* __restrict__ Wv, const float* __restrict__ bv)
{
    __shared__ float buf[64 * 65];   // phase1: xs[16*64] + ws[64*17]; phase2: vsm[64][65]
    float* xs = buf;
    float* ws = buf + 1024;

    const int jt = blockIdx.x;       // key tile (n0 = jt*64)
    const int cb = blockIdx.y;       // channel block (c0 = cb*64)
    const int b  = blockIdx.z;
    const int n0 = jt * 64;
    const int c0 = cb * 64;
    const int t  = threadIdx.x;
    const int tn = t & 15;
    const int tc = t >> 4;

    float acc[4][8];
#pragma unroll
    for (int r = 0; r < 4; r++)
#pragma unroll
        for (int s = 0; s < 8; s++) acc[r][s] = 0.f;

    for (int k0 = 0; k0 < CC_; k0 += 16) {
        for (int i = 0; i < 8; i++) {
            int idx = t + 128 * i;
            int kk = idx >> 6, nn = idx & 63;
            xs[kk * 64 + nn] = x[((size_t)b * CC_ + k0 + kk) * NN + n0 + nn];
        }
        for (int i = 0; i < 8; i++) {
            int idx = t + 128 * i;
            int c = idx >> 4, kk = idx & 15;
            ws[c * 17 + kk] = Wv[(c0 + c) * CC_ + k0 + kk];
        }
        __syncthreads();
#pragma unroll
        for (int kk = 0; kk < 16; kk++) {
            float4 a = *(const float4*)&xs[kk * 64 + tn * 4];
#pragma unroll
            for (int s = 0; s < 8; s++) {
                float w = ws[(tc * 8 + s) * 17 + kk];
                acc[0][s] += a.x * w;
                acc[1][s] += a.y * w;
                acc[2][s] += a.z * w;
                acc[3][s] += a.w * w;
            }
        }
        __syncthreads();
    }

    float* vsm = buf;   // [64 j][65]
#pragma unroll
    for (int r = 0; r < 4; r++)
#pragma unroll
        for (int s = 0; s < 8; s++)
            vsm[(tn * 4 + r) * 65 + tc * 8 + s] = acc[r][s] + bv[c0 + tc * 8 + s];
    __syncthreads();

    // pack fragments: this cb covers ct = cb*8 .. cb*8+7 -> 2048 uints
    uint32_t* dst = g_vf + ((size_t)(b * 64 + jt)) * 8192;
#pragma unroll
    for (int i = 0; i < 16; i++) {
        int idx  = t + 128 * i;          // 0..2047
        int lane = idx & 31;
        int comp = (idx >> 5) & 1;
        int ctl  = (idx >> 6) & 7;
        int kc   = idx >> 9;
        int g    = lane >> 2, i4 = lane & 3;
        int jrow = kc * 16 + comp * 8 + 2 * i4;
        int c    = ctl * 8 + g;
        uint32_t h2 = pack_h2(vsm[jrow * 65 + c], vsm[(jrow + 1) * 65 + c]);
        dst[((kc * 32 + cb * 8 + ctl) * 2 + comp) * 32 + lane] = h2;
    }
}

// ---------------------------------------------------------------------------
// Kernel C: fused flash attention, fp16 mma.sync m16n8k16.
// grid (64, 8), 256 threads (8 warps). CTA = 64 queries x 256 channels.
// S = QK^T with 2-term fp16 split; PV single-pass fp16.
// ---------------------------------------------------------------------------
// byte offsets into dynamic smem:
#define QF_OFF  0                       // uint [2][4mt][2kc][4comp] stride 33 = 2112 u = 8448 B
#define KF_OFF  8448                    // uint [2][2kc][8nt][2comp] stride 33 = 2112 u
#define PP_OFF  16896                   // float p[64][68] = 17408 B
#define PF_OFF  34304                   // uint [2pm][2mt][4kc][4comp] stride 33 = 2112 u
#define VS_OFF  42752                   // uint [8192] = 32768 B
#define MM_OFF  75520                   // float[64]
#define LL_OFF  75776
#define CR_OFF  76032
#define ATTN_SMEM_BYTES 76288

#define QF_IDX(pass,mt,kc,comp) (((((pass)*4+(mt))*2+(kc))*4+(comp))*33)
#define KF_IDX(pass,kc,nt,comp) (((((pass)*2+(kc))*8+(nt))*2+(comp))*33)
#define PF_IDX(pm,mt,kc,comp)   (((((pm)*2+(mt))*4+(kc))*4+(comp))*33)

__global__ __launch_bounds__(256, 2)
void attn_kernel(float* __restrict__ out)
{
    extern __shared__ char smem[];
    uint32_t* qf  = (uint32_t*)(smem + QF_OFF);
    uint32_t* kf  = (uint32_t*)(smem + KF_OFF);
    float*    p   = (float*)(smem + PP_OFF);
    uint32_t* pf  = (uint32_t*)(smem + PF_OFF);
    uint32_t* vs  = (uint32_t*)(smem + VS_OFF);
    uint4*    vs4 = (uint4*)(smem + VS_OFF);
    float*    mrow = (float*)(smem + MM_OFF);
    float*    lrow = (float*)(smem + LL_OFF);
    float*    crow = (float*)(smem + CR_OFF);

    const int b  = blockIdx.y;
    const int q0 = blockIdx.x * 64;
    const int t  = threadIdx.x;
    const int wid  = t >> 5;
    const int lane = t & 31;
    const int g    = lane >> 2;
    const int i4   = lane & 3;

    // S-phase warp map: 16q x 32j tiles
    const int sm = wid & 3;
    const int sn = wid >> 2;
    // PV warp map: 32q x 64c tiles
    const int pm = wid & 1;
    const int pn = wid >> 1;

    // ---- stage Q hi/lo fragments once ----
#pragma unroll
    for (int i = 0; i < 4; i++) {
        int idx = t + 256 * i;                  // 0..1023 (r, d-pair)
        int r = idx >> 4, d2 = idx & 15;
        float2 v = *(const float2*)&g_q[((size_t)b * NN + q0 + r) * DD + 2 * d2];
        __half hx = __float2half_rn(v.x), hy = __float2half_rn(v.y);
        float lx = v.x - __half2float(hx), ly = v.y - __half2float(hy);
        uint32_t hi_u = pack_h2(__half2float(hx), __half2float(hy));
        uint32_t lo_u = pack_h2(lx, ly);
        int mt = r >> 4, rr = r & 15, gg = rr & 7, rh = rr >> 3;
        int kc = d2 >> 3, dk = d2 & 7, ii = dk & 3, kh = dk >> 2;
        int comp = rh + 2 * kh;
        qf[QF_IDX(0, mt, kc, comp) + 4 * gg + ii] = hi_u;
        qf[QF_IDX(1, mt, kc, comp) + 4 * gg + ii] = lo_u;
    }
    if (t < 64) { mrow[t] = -1e30f; lrow[t] = 0.f; }

    float4 o[2][8];
#pragma unroll
    for (int mt = 0; mt < 2; mt++)
#pragma unroll
        for (int nt = 0; nt < 8; nt++) o[mt][nt] = make_float4(0.f, 0.f, 0.f, 0.f);

    __syncthreads();

    for (int jt = 0; jt < 64; jt++) {
        // ---- stage K hi/lo fragments ----
#pragma unroll
        for (int i = 0; i < 4; i++) {
            int idx = t + 256 * i;
            int j = idx >> 4, d2 = idx & 15;
            float2 v = *(const float2*)&g_k[((size_t)b * NN + jt * 64 + j) * DD + 2 * d2];
            __half hx = __float2half_rn(v.x), hy = __float2half_rn(v.y);
            float lx = v.x - __half2float(hx), ly = v.y - __half2float(hy);
            uint32_t hi_u = pack_h2(__half2float(hx), __half2float(hy));
            uint32_t lo_u = pack_h2(lx, ly);
            int nt = j >> 3, gg = j & 7;
            int kc = d2 >> 3, dk = d2 & 7, ii = dk & 3, comp = dk >> 2;
            kf[KF_IDX(0, kc, nt, comp) + 4 * gg + ii] = hi_u;
            kf[KF_IDX(1, kc, nt, comp) + 4 * gg + ii] = lo_u;
        }
        __syncthreads();

        // ---- S = Q.K^T (hi*hi + hi*lo + lo*hi) ----
        float4 sacc[4];
#pragma unroll
        for (int n4 = 0; n4 < 4; n4++) sacc[n4] = make_float4(0.f, 0.f, 0.f, 0.f);
#pragma unroll
        for (int kc = 0; kc < 2; kc++) {
            uint32_t ah[4], al[4];
#pragma unroll
            for (int c = 0; c < 4; c++) {
                ah[c] = qf[QF_IDX(0, sm, kc, c) + lane];
                al[c] = qf[QF_IDX(1, sm, kc, c) + lane];
            }
#pragma unroll
            for (int n4 = 0; n4 < 4; n4++) {
                int nt = sn * 4 + n4;
                uint32_t bh0 = kf[KF_IDX(0, kc, nt, 0) + lane];
                uint32_t bh1 = kf[KF_IDX(0, kc, nt, 1) + lane];
                uint32_t bl0 = kf[KF_IDX(1, kc, nt, 0) + lane];
                uint32_t bl1 = kf[KF_IDX(1, kc, nt, 1) + lane];
                mma_f16(sacc[n4], ah[0], ah[1], ah[2], ah[3], bh0, bh1);
                mma_f16(sacc[n4], ah[0], ah[1], ah[2], ah[3], bl0, bl1);
                mma_f16(sacc[n4], al[0], al[1], al[2], al[3], bh0, bh1);
            }
        }
#pragma unroll
        for (int n4 = 0; n4 < 4; n4++) {
            int row = sm * 16 + g;
            int col = sn * 32 + n4 * 8 + i4 * 2;
            *(float2*)&p[row * 68 + col]       = make_float2(sacc[n4].x, sacc[n4].y);
            *(float2*)&p[(row + 8) * 68 + col] = make_float2(sacc[n4].z, sacc[n4].w);
        }
        __syncthreads();

        // ---- online softmax, 4 threads/row; writes fp16 A-fragments of P ----
        {
            int r = t >> 2, qd = t & 3;
            float* pr = p + r * 68 + qd * 16;
            float4 x0 = *(float4*)(pr + 0);
            float4 x1 = *(float4*)(pr + 4);
            float4 x2 = *(float4*)(pr + 8);
            float4 x3 = *(float4*)(pr + 12);
            float lm = fmaxf(fmaxf(fmaxf(x0.x, x0.y), fmaxf(x0.z, x0.w)),
                             fmaxf(fmaxf(x1.x, x1.y), fmaxf(x1.z, x1.w)));
            lm = fmaxf(lm, fmaxf(fmaxf(fmaxf(x2.x, x2.y), fmaxf(x2.z, x2.w)),
                                 fmaxf(fmaxf(x3.x, x3.y), fmaxf(x3.z, x3.w))));
            lm = fmaxf(lm, __shfl_xor_sync(0xffffffffu, lm, 1, 4));
            lm = fmaxf(lm, __shfl_xor_sync(0xffffffffu, lm, 2, 4));
            float mold = mrow[r];
            float mx = fmaxf(mold, lm);
            float e[16];
            e[0]=__expf(x0.x-mx); e[1]=__expf(x0.y-mx); e[2]=__expf(x0.z-mx); e[3]=__expf(x0.w-mx);
            e[4]=__expf(x1.x-mx); e[5]=__expf(x1.y-mx); e[6]=__expf(x1.z-mx); e[7]=__expf(x1.w-mx);
            e[8]=__expf(x2.x-mx); e[9]=__expf(x2.y-mx); e[10]=__expf(x2.z-mx); e[11]=__expf(x2.w-mx);
            e[12]=__expf(x3.x-mx); e[13]=__expf(x3.y-mx); e[14]=__expf(x3.z-mx); e[15]=__expf(x3.w-mx);
            float s = 0.f;
#pragma unroll
            for (int q = 0; q < 16; q++) s += e[q];
            // write fragment-ordered half2 P
            int ppm = r >> 5, pmt = (r >> 4) & 1, gg = r & 7, rh = (r >> 3) & 1;
#pragma unroll
            for (int prr = 0; prr < 8; prr++) {
                int ii = prr & 3, jh = prr >> 2;
                int comp = rh + 2 * jh;
                pf[PF_IDX(ppm, pmt, qd, comp) + 4 * gg + ii] = pack_h2(e[2*prr], e[2*prr+1]);
            }
            s += __shfl_xor_sync(0xffffffffu, s, 1, 4);
            s += __shfl_xor_sync(0xffffffffu, s, 2, 4);
            if (qd == 0) {
                float corr = __expf(mold - mx);
                crow[r] = corr;
                mrow[r] = mx;
                lrow[r] = lrow[r] * corr + s;
            }
        }
        __syncthreads();

        // ---- rescale accumulators ----
#pragma unroll
        for (int mt = 0; mt < 2; mt++) {
            float cf0 = crow[pm * 32 + mt * 16 + g];
            float cf1 = crow[pm * 32 + mt * 16 + g + 8];
#pragma unroll
            for (int nt = 0; nt < 8; nt++) {
                o[mt][nt].x *= cf0; o[mt][nt].y *= cf0;
                o[mt][nt].z *= cf1; o[mt][nt].w *= cf1;
            }
        }

        // ---- stage V (32KB, verbatim fragment copy) ----
        {
            const uint4* src = (const uint4*)(g_vf + ((size_t)(b * 64 + jt)) * 8192);
#pragma unroll
            for (int i = 0; i < 8; i++)
                vs4[t + 256 * i] = src[t + 256 * i];
        }
        __syncthreads();

        // ---- PV ----
#pragma unroll
        for (int kc = 0; kc < 4; kc++) {
            uint32_t a0[4], a1[4];
#pragma unroll
            for (int c = 0; c < 4; c++) {
                a0[c] = pf[PF_IDX(pm, 0, kc, c) + lane];
                a1[c] = pf[PF_IDX(pm, 1, kc, c) + lane];
            }
#pragma unroll
            for (int nt = 0; nt < 8; nt++) {
                int ct = pn * 8 + nt;
                uint32_t b0 = vs[((kc * 32 + ct) * 2 + 0) * 32 + lane];
                uint32_t b1 = vs[((kc * 32 + ct) * 2 + 1) * 32 + lane];
                mma_f16(o[0][nt], a0[0], a0[1], a0[2], a0[3], b0, b1);
                mma_f16(o[1][nt], a1[0], a1[1], a1[2], a1[3], b0, b1);
            }
        }
        __syncthreads();
    }

    // ---- epilogue: out[b][c][n], normalize by l ----
#pragma unroll
    for (int mt = 0; mt < 2; mt++) {
        int qb = q0 + pm * 32 + mt * 16;
        float il0 = 1.0f / lrow[pm * 32 + mt * 16 + g];
        float il1 = 1.0f / lrow[pm * 32 + mt * 16 + g + 8];
#pragma unroll
        for (int nt = 0; nt < 8; nt++) {
            int c = pn * 64 + nt * 8 + i4 * 2;
            out[((size_t)b * CC_ + c)     * NN + qb + g]     = o[mt][nt].x * il0;
            out[((size_t)b * CC_ + c + 1) * NN + qb + g]     = o[mt][nt].y * il0;
            out[((size_t)b * CC_ + c)     * NN + qb + g + 8] = o[mt][nt].z * il1;
            out[((size_t)b * CC_ + c + 1) * NN + qb + g + 8] = o[mt][nt].w * il1;
        }
    }
}

// ---------------------------------------------------------------------------
extern "C" void kernel_launch(void* const* d_in, const int* in_sizes, int n_in,
                              void* d_out, int out_size)
{
    const float* x  = (const float*)d_in[0];
    const float* Wq = (const float*)d_in[1];
    const float* bq = (const float*)d_in[2];
    const float* Wk = (const float*)d_in[3];
    const float* bk = (const float*)d_in[4];
    const float* Wv = (const float*)d_in[5];
    const float* bv = (const float*)d_in[6];
    float* out = (float*)d_out;

    qk_proj_kernel<<<dim3(32, 8), 128>>>(x, Wq, bq, Wk, bk);
    v_proj_kernel<<<dim3(64, 4, 8), 128>>>(x, Wv, bv);

    cudaFuncSetAttribute(attn_kernel, cudaFuncAttributeMaxDynamicSharedMemorySize,
                         ATTN_SMEM_BYTES);
    attn_kernel<<<dim3(64, 8), 256, ATTN_SMEM_BYTES>>>(out);
}